// round 14
// baseline (speedup 1.0000x reference)
#include <cuda_runtime.h>
#include <cuda_bf16.h>

#define BB 16
#define CC 528
#define CC4 132         // CC/4
#define TT 32
#define HH 28
#define WW 28
#define HW 784          // 28*28
#define HW4 196         // HW/4 (7 float4 groups per row)
#define RR 256
#define MAX_ITEMS (BB*CC*HW4)   // 1,655,808
#define MEAN_BLOCKS ((MAX_ITEMS + 255) / 256)  // 6468
#define CPB 88          // channels per roi-block (6 * 88 = 528)
#define CPW 11          // channels per warp (8 warps * 11 = 88)
#define NJG 16          // j-groups in mlp (16 groups x 8 neurons)

typedef unsigned long long ull;

// packed f32x2 fma: d = a*b + c on both halves (FFMA2 — PTX-only pattern)
__device__ __forceinline__ ull ffma2(ull a, ull b, ull c) {
    ull d;
    asm("fma.rn.f32x2 %0, %1, %2, %3;" : "=l"(d) : "l"(a), "l"(b), "l"(c));
    return d;
}
__device__ __forceinline__ float hsum2(ull a) {
    return __uint_as_float((unsigned)a) + __uint_as_float((unsigned)(a >> 32));
}

// ---- device scratch (no allocations allowed) ----
__device__ float  g_wmap[RR * HW];    // per-ROI dense weight map over 28x28 (zero outside support)
__device__ int4   g_rect[RR];         // padded rect: xmin,xmax,ymin,ymax (inclusive); xmin>xmax => empty
__device__ int    g_broi[RR];         // batch index per roi
__device__ float4 g_rmean4[RR * CC4]; // pooled ROI features (float4 layout for vector MLP)
__device__ float  g_v[128];           // folded w3 @ w2  (layers 2+3 are linear)
__device__ float  g_c0;               // folded bias
__device__ float  g_part[RR * NJG];   // per-(roi, j-group) partial sums
__device__ int    g_load[BB][HW4];    // per-batch compacted float4-group indices
__device__ int    g_nload[BB];        // count per batch
__device__ float4 g_feat4[BB * CC * HW4];  // temporal-mean features (26.5 MB, L2-resident)
                                           // uncovered entries stay 0 (zero-initialized, never written)

// ============================================================
// Kernel 0 (fully fused prep), 273 blocks:
//   blocks 0..255  : per-ROI dense weight map (wmap)
//   blocks 256..271: per-batch cover: analytic rects + union mask + load list
//   block  272     : fold v = w3@w2, c0 = w3@b2 + b3
// Stored rects padded 1px: padded pixels have wmap == 0 and feat == 0,
// contributing exactly 0 (immunizes against 1-ulp rect/wmap divergence).
// ============================================================
__global__ void wp_kernel(const float* __restrict__ bbox,
                          const float* __restrict__ w2,
                          const float* __restrict__ b2,
                          const float* __restrict__ w3,
                          const float* __restrict__ b3) {
    const int tid = threadIdx.x;
    const int blk = blockIdx.x;

    if (blk == 272) {                        // fold layers 2+3
        int j = tid;
        if (j < 128) {
            float acc = 0.f;
            #pragma unroll
            for (int i = 0; i < 32; ++i) acc += w3[i] * w2[i * 128 + j];
            g_v[j] = acc;
            if (j == 0) {
                float c = b3[0];
                #pragma unroll
                for (int i = 0; i < 32; ++i) c += w3[i] * b2[i];
                g_c0 = c;
            }
        }
        return;
    }

    if (blk >= 256) {                        // ---- cover for batch b ----
        const int b = blk - 256;
        __shared__ unsigned char mask[HW4];
        __shared__ int4 srect[RR];           // unpadded rects of this batch's rois
        __shared__ int scnt;

        for (int i = tid; i < HW4; i += 256) mask[i] = 0;
        if (tid == 0) scnt = 0;
        __syncthreads();

        // one thread per roi: analytic rect (separable x/y bounds)
        {
            const float* bb = bbox + tid * 5;
            const int rb = (int)bb[0];
            if (rb == b) {
                const float x1 = bb[1] * 0.0625f - 0.5f;
                const float y1 = bb[2] * 0.0625f - 0.5f;
                const float x2 = bb[3] * 0.0625f - 0.5f;
                const float y2 = bb[4] * 0.0625f - 0.5f;
                const float bw = (x2 - x1) * 0.125f;
                const float bh = (y2 - y1) * 0.125f;
                int xmin = 1000, xmax = -1, ymin = 1000, ymax = -1;
                #pragma unroll
                for (int i = 0; i < 16; ++i) {
                    const float o = (float)i * 0.5f + 0.25f;
                    const float sx = x1 + o * bw;
                    if (sx > -1.0f && sx < (float)WW) {
                        float xc = fminf(fmaxf(sx, 0.f), (float)(WW - 1));
                        int x0 = (int)floorf(xc);
                        int x1i = min(x0 + 1, WW - 1);
                        xmin = min(xmin, x0); xmax = max(xmax, x1i);
                    }
                    const float sy = y1 + o * bh;
                    if (sy > -1.0f && sy < (float)HH) {
                        float yc = fminf(fmaxf(sy, 0.f), (float)(HH - 1));
                        int y0 = (int)floorf(yc);
                        int y1i = min(y0 + 1, HH - 1);
                        ymin = min(ymin, y0); ymax = max(ymax, y1i);
                    }
                }
                int4 rc_pad, rc_raw;
                if (xmax < 0 || ymax < 0) {
                    rc_pad = make_int4(1000, -1, 1000, -1);
                    rc_raw = rc_pad;
                } else {
                    rc_raw = make_int4(xmin, xmax, ymin, ymax);
                    rc_pad = make_int4(max(xmin - 1, 0), min(xmax + 1, WW - 1),
                                       max(ymin - 1, 0), min(ymax + 1, HH - 1));
                }
                g_rect[tid] = rc_pad;
                g_broi[tid] = rb;
                if (rc_raw.x <= rc_raw.y) {
                    int slot = atomicAdd(&scnt, 1);
                    srect[slot] = rc_raw;    // order irrelevant: mask union idempotent
                }
            }
        }
        __syncthreads();

        const int n = scnt;
        for (int r = 0; r < n; ++r) {
            const int4 rc = srect[r];
            const int g0 = rc.x >> 2, g1 = rc.y >> 2;
            const int cols = g1 - g0 + 1;
            const int tot = (rc.w - rc.z + 1) * cols;
            for (int i = tid; i < tot; i += 256) {
                int ry = i / cols, cx = i - ry * cols;
                mask[(rc.z + ry) * 7 + g0 + cx] = 1;
            }
        }
        __syncthreads();

        // warp-0 ballot compaction (replaces 196-iter serial loop)
        if (tid < 32) {
            const int lane = tid;
            int base = 0;
            #pragma unroll
            for (int ch = 0; ch < 7; ++ch) {
                const int i = ch * 32 + lane;
                const bool m = (i < HW4) && mask[i];
                const unsigned bal = __ballot_sync(0xffffffffu, m);
                if (m) g_load[b][base + __popc(bal & ((1u << lane) - 1))] = i;
                base += __popc(bal);
            }
            if (lane == 0) g_nload[b] = base;
        }
        return;
    }

    // ---- wmap for roi = blk ----
    __shared__ float smap[HW];
    const int roi = blk;

    for (int p = tid; p < HW; p += 256) smap[p] = 0.f;
    __syncthreads();

    const float* bb = bbox + roi * 5;
    const float x1 = bb[1] * 0.0625f - 0.5f;
    const float y1 = bb[2] * 0.0625f - 0.5f;
    const float x2 = bb[3] * 0.0625f - 0.5f;
    const float y2 = bb[4] * 0.0625f - 0.5f;
    const float bw = (x2 - x1) * 0.125f;   // /OUT(8)
    const float bh = (y2 - y1) * 0.125f;

    const int iy = tid >> 4, ix = tid & 15;
    const float sy = y1 + ((float)iy * 0.5f + 0.25f) * bh;  // off=(i+0.5)/SR
    const float sx = x1 + ((float)ix * 0.5f + 0.25f) * bw;

    const bool valid = (sy > -1.0f) && (sy < (float)HH) && (sx > -1.0f) && (sx < (float)WW);
    if (valid) {
        float yc = fminf(fmaxf(sy, 0.f), (float)(HH - 1));
        float xc = fminf(fmaxf(sx, 0.f), (float)(WW - 1));
        int y0 = (int)floorf(yc);
        int x0 = (int)floorf(xc);
        int y1i = min(y0 + 1, HH - 1);
        int x1i = min(x0 + 1, WW - 1);
        float ly = yc - (float)y0, lx = xc - (float)x0;
        float hy = 1.f - ly, hx = 1.f - lx;
        const float s = 1.0f / 256.0f;   // uniform mean over 16x16 samples
        atomicAdd(&smap[y0 * WW + x0],  hy * hx * s);
        atomicAdd(&smap[y0 * WW + x1i], hy * lx * s);
        atomicAdd(&smap[y1i * WW + x0], ly * hx * s);
        atomicAdd(&smap[y1i * WW + x1i], ly * lx * s);
    }
    __syncthreads();

    for (int p = tid; p < HW; p += 256) g_wmap[roi * HW + p] = smap[p];
}

// ============================================================
// Kernel 1 (HBM-bound, 81% DRAM — unchanged): temporal mean over
// covered groups, flat work list, 4 independent accumulator chains.
// ============================================================
__global__ void __launch_bounds__(256) mean_kernel(const float* __restrict__ x) {
    __shared__ int soff[BB + 1];
    __shared__ int sn4[BB];
    if (threadIdx.x == 0) {
        int acc = 0;
        #pragma unroll
        for (int b = 0; b < BB; ++b) {
            soff[b] = acc;
            int n = g_nload[b];
            sn4[b] = n;
            acc += n * CC;
        }
        soff[BB] = acc;
    }
    __syncthreads();

    const int item = blockIdx.x * 256 + threadIdx.x;
    if (item >= soff[BB]) return;

    int b = 0;
    while (item >= soff[b + 1]) ++b;
    const int rel = item - soff[b];
    const int n4 = sn4[b];
    const int c = rel / n4;
    const int j = rel - c * n4;
    const int p4 = g_load[b][j];
    const int plane = b * CC + c;

    const float4* __restrict__ xp =
        (const float4*)x + (size_t)plane * (TT * HW4) + p4;

    float4 a0 = make_float4(0.f, 0.f, 0.f, 0.f);
    float4 a1 = a0, a2 = a0, a3 = a0;
    #pragma unroll
    for (int t = 0; t < 8; ++t) {
        float4 v0 = __ldcs(xp + (t)      * HW4);
        float4 v1 = __ldcs(xp + (t + 8)  * HW4);
        float4 v2 = __ldcs(xp + (t + 16) * HW4);
        float4 v3 = __ldcs(xp + (t + 24) * HW4);
        a0.x += v0.x; a0.y += v0.y; a0.z += v0.z; a0.w += v0.w;
        a1.x += v1.x; a1.y += v1.y; a1.z += v1.z; a1.w += v1.w;
        a2.x += v2.x; a2.y += v2.y; a2.z += v2.z; a2.w += v2.w;
        a3.x += v3.x; a3.y += v3.y; a3.z += v3.z; a3.w += v3.w;
    }
    const float inv = 1.0f / (float)TT;
    g_feat4[(size_t)plane * HW4 + p4] = make_float4(
        (a0.x + a1.x + a2.x + a3.x) * inv,
        (a0.y + a1.y + a2.y + a3.y) * inv,
        (a0.z + a1.z + a2.z + a3.z) * inv,
        (a0.w + a1.w + a2.w + a3.w) * inv);
}

// ============================================================
// Kernel 2: ROI pooling; lane layout adapts to rect width so narrow
// rects (the common case) keep all 32 lanes busy:
//   w <= 8  : 8 lanes x, 4 rows/iter
//   w <= 16 : 16 lanes x, 2 rows/iter
//   else    : 32 lanes x, 1 row/iter
// 11 channels per warp (independent L2 streams), wmap smem-staged.
// ============================================================
template <int XL>   // lanes along x (8, 16 or 32)
__device__ __forceinline__ void roi_accum(
    const float* __restrict__ fp0, const float* wm_s,
    const int4 rc, const int lane, float* a) {
    const int xx = rc.x + (lane & (XL - 1));
    const int yo = lane / XL;                 // 0..(32/XL-1)
    const bool on = (xx <= rc.y);
    #pragma unroll 2
    for (int yy = rc.z + yo; yy <= rc.w; yy += 32 / XL) {
        const int p = yy * WW + xx;
        if (on) {
            const float w = wm_s[p];
            #pragma unroll
            for (int k = 0; k < CPW; ++k)
                a[k] += w * fp0[k * HW + p];
        }
    }
}

__global__ void __launch_bounds__(256) roi_kernel() {
    __shared__ float wm_s[HW];
    const int roi = blockIdx.x;
    const int cg  = blockIdx.y;            // 0..5
    const int tid = threadIdx.x, warp = tid >> 5, lane = tid & 31;

    const int4 rc = g_rect[roi];
    float* __restrict__ rmean = (float*)g_rmean4;
    if (rc.x > rc.y) {                     // empty roi (uniform branch)
        if (tid < CPB) rmean[roi * CC + cg * CPB + tid] = 0.f;
        return;
    }

    for (int p = tid; p < HW; p += 256) wm_s[p] = g_wmap[roi * HW + p];
    __syncthreads();

    const int b = g_broi[roi];
    const int c0 = cg * CPB + warp * CPW;
    const float* __restrict__ fp0 =
        (const float*)g_feat4 + (size_t)(b * CC + c0) * HW;

    float a[CPW];
    #pragma unroll
    for (int k = 0; k < CPW; ++k) a[k] = 0.f;

    const int wspan = rc.y - rc.x + 1;     // uniform across block
    if (wspan <= 8)       roi_accum<8>(fp0, wm_s, rc, lane, a);
    else if (wspan <= 16) roi_accum<16>(fp0, wm_s, rc, lane, a);
    else                  roi_accum<32>(fp0, wm_s, rc, lane, a);

    #pragma unroll
    for (int k = 0; k < CPW; ++k) {
        #pragma unroll
        for (int o = 16; o; o >>= 1) a[k] += __shfl_xor_sync(0xffffffffu, a[k], o);
    }
    if (lane == 0) {
        float* __restrict__ dst = rmean + roi * CC + c0;
        #pragma unroll
        for (int k = 0; k < CPW; ++k) dst[k] = a[k];
    }
}

// ============================================================
// Kernel 3: layer-1 GEMV partials with packed f32x2 math (FFMA2).
// w1 rows and r4 tiles are 16B-aligned: reinterpret float4 as ulonglong2
// -> each b64 reg is an f32 pair, zero packing cost. 8 FFMA2 + 5 loads
// per iteration (vs 16 FFMA + 5 loads scalar). 1024 blocks, NJG=16.
// ============================================================
__global__ void __launch_bounds__(256) mlp_kernel(
    const float* __restrict__ w1, const float* __restrict__ b1) {
    __shared__ ulonglong2 r4[4 * CC4];
    __shared__ float part[8][4];
    const int tid = threadIdx.x, warp = tid >> 5, lane = tid & 31;
    const int roi0 = blockIdx.x * 4;
    const int jg = blockIdx.y;

    const ulonglong2* __restrict__ src = (const ulonglong2*)g_rmean4;
    for (int i = tid; i < 4 * CC4; i += 256)
        r4[i] = src[roi0 * CC4 + i];
    __syncthreads();

    const int j = jg * 8 + warp;
    const ulonglong2* __restrict__ wr = (const ulonglong2*)(w1 + j * CC);

    ull a0 = 0ull, a1 = 0ull, a2 = 0ull, a3 = 0ull;   // packed (+0,+0)
    for (int k = lane; k < CC4; k += 32) {
        const ulonglong2 w = wr[k];
        const ulonglong2 v0 = r4[k];
        const ulonglong2 v1 = r4[CC4 + k];
        const ulonglong2 v2 = r4[2 * CC4 + k];
        const ulonglong2 v3 = r4[3 * CC4 + k];
        a0 = ffma2(w.x, v0.x, a0); a0 = ffma2(w.y, v0.y, a0);
        a1 = ffma2(w.x, v1.x, a1); a1 = ffma2(w.y, v1.y, a1);
        a2 = ffma2(w.x, v2.x, a2); a2 = ffma2(w.y, v2.y, a2);
        a3 = ffma2(w.x, v3.x, a3); a3 = ffma2(w.y, v3.y, a3);
    }
    float s0 = hsum2(a0), s1 = hsum2(a1), s2 = hsum2(a2), s3 = hsum2(a3);
    #pragma unroll
    for (int o = 16; o; o >>= 1) {
        s0 += __shfl_xor_sync(0xffffffffu, s0, o);
        s1 += __shfl_xor_sync(0xffffffffu, s1, o);
        s2 += __shfl_xor_sync(0xffffffffu, s2, o);
        s3 += __shfl_xor_sync(0xffffffffu, s3, o);
    }
    if (lane == 0) {
        float bj = b1[j], vj = g_v[j];
        part[warp][0] = vj * fmaxf(s0 + bj, 0.f);
        part[warp][1] = vj * fmaxf(s1 + bj, 0.f);
        part[warp][2] = vj * fmaxf(s2 + bj, 0.f);
        part[warp][3] = vj * fmaxf(s3 + bj, 0.f);
    }
    __syncthreads();
    if (tid < 4) {
        float s = 0.f;
        #pragma unroll
        for (int w = 0; w < 8; ++w) s += part[w][tid];
        g_part[(roi0 + tid) * NJG + jg] = s;
    }
}

// ============================================================
// Kernel 4: finalize. out[roi] = c0 + sum_jg part[roi][jg].
// ============================================================
__global__ void fin_kernel(float* __restrict__ out) {
    int roi = threadIdx.x;
    float s = g_c0;
    #pragma unroll
    for (int jg = 0; jg < NJG; ++jg) s += g_part[roi * NJG + jg];
    out[roi] = s;
}

// ============================================================
// launch
// ============================================================
extern "C" void kernel_launch(void* const* d_in, const int* in_sizes, int n_in,
                              void* d_out, int out_size) {
    const float* x    = (const float*)d_in[0];
    const float* bbox = (const float*)d_in[1];
    const float* w1   = (const float*)d_in[2];
    const float* b1   = (const float*)d_in[3];
    const float* w2   = (const float*)d_in[4];
    const float* b2   = (const float*)d_in[5];
    const float* w3   = (const float*)d_in[6];
    const float* b3   = (const float*)d_in[7];
    float* out = (float*)d_out;

    wp_kernel<<<273, 256>>>(bbox, w2, b2, w3, b3);
    mean_kernel<<<MEAN_BLOCKS, 256>>>(x);
    roi_kernel<<<dim3(RR, CC / CPB), 256>>>();
    mlp_kernel<<<dim3(RR / 4, NJG), 256>>>(w1, b1);
    fin_kernel<<<1, RR>>>(out);
}

// round 15
// speedup vs baseline: 1.0627x; 1.0627x over previous
#include <cuda_runtime.h>
#include <cuda_bf16.h>

#define BB 16
#define CC 528
#define CC4 132         // CC/4
#define TT 32
#define HH 28
#define WW 28
#define HW 784          // 28*28
#define HW4 196         // HW/4 (7 float4 groups per row)
#define RR 256
#define MAX_ITEMS (BB*CC*HW4)   // 1,655,808
#define MEAN_BLOCKS ((MAX_ITEMS + 255) / 256)  // 6468
#define CPB 88          // channels per roi-block (6 * 88 = 528)
#define CPW 11          // channels per warp (8 warps * 11 = 88)
#define NJG 16          // j-groups in mlp (16 groups x 8 neurons)

typedef unsigned long long ull;

// packed f32x2 fma: d = a*b + c on both halves (FFMA2 — PTX-only pattern)
__device__ __forceinline__ ull ffma2(ull a, ull b, ull c) {
    ull d;
    asm("fma.rn.f32x2 %0, %1, %2, %3;" : "=l"(d) : "l"(a), "l"(b), "l"(c));
    return d;
}
__device__ __forceinline__ float hsum2(ull a) {
    return __uint_as_float((unsigned)a) + __uint_as_float((unsigned)(a >> 32));
}

// ---- device scratch (no allocations allowed) ----
__device__ float  g_wx[RR][WW];       // separable ROI weights: wmap = WY ⊗ WX
__device__ float  g_wy[RR][HH];       // (zero outside support)
__device__ int4   g_rect[RR];         // padded rect: xmin,xmax,ymin,ymax (inclusive); xmin>xmax => empty
__device__ int    g_broi[RR];         // batch index per roi
__device__ float4 g_rmean4[RR * CC4]; // pooled ROI features (float4 layout for vector MLP)
__device__ float  g_v[128];           // folded w3 @ w2  (layers 2+3 are linear)
__device__ float  g_c0;               // folded bias
__device__ float  g_part[RR * NJG];   // per-(roi, j-group) partial sums
__device__ int    g_load[BB][HW4];    // per-batch compacted float4-group indices
__device__ int    g_nload[BB];        // count per batch
__device__ float4 g_feat4[BB * CC * HW4 + 16];  // temporal-mean features (26.5 MB, L2-resident)
                                                // +16 pad: roi's branch-free loads may run past the
                                                // last plane; pad is zero, weighted by wxv=0.
                                                // uncovered entries stay 0 (zero-initialized, never written)

// ============================================================
// Kernel 0 (fully fused prep), 273 blocks:
//   blocks 0..255  : per-ROI separable weights WX[28], WY[28]
//   blocks 256..271: per-batch cover: analytic rects + union mask + load list
//   block  272     : fold v = w3@w2, c0 = w3@b2 + b3
// wmap = WY ⊗ WX exactly (bilinear kernel + validity are separable);
// 1/256 sample-mean split as 1/16 into each factor.
// Stored rects padded 1px: padded pixels have WX or WY == 0 and feat == 0.
// ============================================================
__global__ void wp_kernel(const float* __restrict__ bbox,
                          const float* __restrict__ w2,
                          const float* __restrict__ b2,
                          const float* __restrict__ w3,
                          const float* __restrict__ b3) {
    const int tid = threadIdx.x;
    const int blk = blockIdx.x;

    if (blk == 272) {                        // fold layers 2+3
        int j = tid;
        if (j < 128) {
            float acc = 0.f;
            #pragma unroll
            for (int i = 0; i < 32; ++i) acc += w3[i] * w2[i * 128 + j];
            g_v[j] = acc;
            if (j == 0) {
                float c = b3[0];
                #pragma unroll
                for (int i = 0; i < 32; ++i) c += w3[i] * b2[i];
                g_c0 = c;
            }
        }
        return;
    }

    if (blk >= 256) {                        // ---- cover for batch b ----
        const int b = blk - 256;
        __shared__ unsigned char mask[HW4];
        __shared__ int4 srect[RR];           // unpadded rects of this batch's rois
        __shared__ int scnt;

        for (int i = tid; i < HW4; i += 256) mask[i] = 0;
        if (tid == 0) scnt = 0;
        __syncthreads();

        // one thread per roi: analytic rect (separable x/y bounds)
        {
            const float* bb = bbox + tid * 5;
            const int rb = (int)bb[0];
            if (rb == b) {
                const float x1 = bb[1] * 0.0625f - 0.5f;
                const float y1 = bb[2] * 0.0625f - 0.5f;
                const float x2 = bb[3] * 0.0625f - 0.5f;
                const float y2 = bb[4] * 0.0625f - 0.5f;
                const float bw = (x2 - x1) * 0.125f;
                const float bh = (y2 - y1) * 0.125f;
                int xmin = 1000, xmax = -1, ymin = 1000, ymax = -1;
                #pragma unroll
                for (int i = 0; i < 16; ++i) {
                    const float o = (float)i * 0.5f + 0.25f;
                    const float sx = x1 + o * bw;
                    if (sx > -1.0f && sx < (float)WW) {
                        float xc = fminf(fmaxf(sx, 0.f), (float)(WW - 1));
                        int x0 = (int)floorf(xc);
                        int x1i = min(x0 + 1, WW - 1);
                        xmin = min(xmin, x0); xmax = max(xmax, x1i);
                    }
                    const float sy = y1 + o * bh;
                    if (sy > -1.0f && sy < (float)HH) {
                        float yc = fminf(fmaxf(sy, 0.f), (float)(HH - 1));
                        int y0 = (int)floorf(yc);
                        int y1i = min(y0 + 1, HH - 1);
                        ymin = min(ymin, y0); ymax = max(ymax, y1i);
                    }
                }
                int4 rc_pad, rc_raw;
                if (xmax < 0 || ymax < 0) {
                    rc_pad = make_int4(1000, -1, 1000, -1);
                    rc_raw = rc_pad;
                } else {
                    rc_raw = make_int4(xmin, xmax, ymin, ymax);
                    rc_pad = make_int4(max(xmin - 1, 0), min(xmax + 1, WW - 1),
                                       max(ymin - 1, 0), min(ymax + 1, HH - 1));
                }
                g_rect[tid] = rc_pad;
                g_broi[tid] = rb;
                if (rc_raw.x <= rc_raw.y) {
                    int slot = atomicAdd(&scnt, 1);
                    srect[slot] = rc_raw;    // order irrelevant: mask union idempotent
                }
            }
        }
        __syncthreads();

        const int n = scnt;
        for (int r = 0; r < n; ++r) {
            const int4 rc = srect[r];
            const int g0 = rc.x >> 2, g1 = rc.y >> 2;
            const int cols = g1 - g0 + 1;
            const int tot = (rc.w - rc.z + 1) * cols;
            for (int i = tid; i < tot; i += 256) {
                int ry = i / cols, cx = i - ry * cols;
                mask[(rc.z + ry) * 7 + g0 + cx] = 1;
            }
        }
        __syncthreads();

        // warp-0 ballot compaction
        if (tid < 32) {
            const int lane = tid;
            int base = 0;
            #pragma unroll
            for (int ch = 0; ch < 7; ++ch) {
                const int i = ch * 32 + lane;
                const bool m = (i < HW4) && mask[i];
                const unsigned bal = __ballot_sync(0xffffffffu, m);
                if (m) g_load[b][base + __popc(bal & ((1u << lane) - 1))] = i;
                base += __popc(bal);
            }
            if (lane == 0) g_nload[b] = base;
        }
        return;
    }

    // ---- separable weights for roi = blk ----
    __shared__ float wx_s[WW], wy_s[HH];
    const int roi = blk;

    if (tid < WW) wx_s[tid] = 0.f;
    if (tid < HH) wy_s[tid] = 0.f;
    __syncthreads();

    const float* bb = bbox + roi * 5;
    const float x1 = bb[1] * 0.0625f - 0.5f;
    const float y1 = bb[2] * 0.0625f - 0.5f;
    const float x2 = bb[3] * 0.0625f - 0.5f;
    const float y2 = bb[4] * 0.0625f - 0.5f;
    const float bw = (x2 - x1) * 0.125f;   // /OUT(8)
    const float bh = (y2 - y1) * 0.125f;
    const float s = 1.0f / 16.0f;          // 1/256 split across the two factors

    if (tid < 16) {                        // x-samples
        const float sx = x1 + ((float)tid * 0.5f + 0.25f) * bw;
        if (sx > -1.0f && sx < (float)WW) {
            float xc = fminf(fmaxf(sx, 0.f), (float)(WW - 1));
            int x0 = (int)floorf(xc);
            int x1i = min(x0 + 1, WW - 1);
            float lx = xc - (float)x0;
            atomicAdd(&wx_s[x0],  (1.f - lx) * s);
            atomicAdd(&wx_s[x1i], lx * s);
        }
    } else if (tid < 32) {                 // y-samples
        const int i = tid - 16;
        const float sy = y1 + ((float)i * 0.5f + 0.25f) * bh;
        if (sy > -1.0f && sy < (float)HH) {
            float yc = fminf(fmaxf(sy, 0.f), (float)(HH - 1));
            int y0 = (int)floorf(yc);
            int y1i = min(y0 + 1, HH - 1);
            float ly = yc - (float)y0;
            atomicAdd(&wy_s[y0],  (1.f - ly) * s);
            atomicAdd(&wy_s[y1i], ly * s);
        }
    }
    __syncthreads();

    if (tid < WW) g_wx[roi][tid] = wx_s[tid];
    if (tid < HH) g_wy[roi][tid] = wy_s[tid];
}

// ============================================================
// Kernel 1 (HBM-bound, 81% DRAM — unchanged): temporal mean over
// covered groups, flat work list, 4 independent accumulator chains.
// ============================================================
__global__ void __launch_bounds__(256) mean_kernel(const float* __restrict__ x) {
    __shared__ int soff[BB + 1];
    __shared__ int sn4[BB];
    if (threadIdx.x == 0) {
        int acc = 0;
        #pragma unroll
        for (int b = 0; b < BB; ++b) {
            soff[b] = acc;
            int n = g_nload[b];
            sn4[b] = n;
            acc += n * CC;
        }
        soff[BB] = acc;
    }
    __syncthreads();

    const int item = blockIdx.x * 256 + threadIdx.x;
    if (item >= soff[BB]) return;

    int b = 0;
    while (item >= soff[b + 1]) ++b;
    const int rel = item - soff[b];
    const int n4 = sn4[b];
    const int c = rel / n4;
    const int j = rel - c * n4;
    const int p4 = g_load[b][j];
    const int plane = b * CC + c;

    const float4* __restrict__ xp =
        (const float4*)x + (size_t)plane * (TT * HW4) + p4;

    float4 a0 = make_float4(0.f, 0.f, 0.f, 0.f);
    float4 a1 = a0, a2 = a0, a3 = a0;
    #pragma unroll
    for (int t = 0; t < 8; ++t) {
        float4 v0 = __ldcs(xp + (t)      * HW4);
        float4 v1 = __ldcs(xp + (t + 8)  * HW4);
        float4 v2 = __ldcs(xp + (t + 16) * HW4);
        float4 v3 = __ldcs(xp + (t + 24) * HW4);
        a0.x += v0.x; a0.y += v0.y; a0.z += v0.z; a0.w += v0.w;
        a1.x += v1.x; a1.y += v1.y; a1.z += v1.z; a1.w += v1.w;
        a2.x += v2.x; a2.y += v2.y; a2.z += v2.z; a2.w += v2.w;
        a3.x += v3.x; a3.y += v3.y; a3.z += v3.z; a3.w += v3.w;
    }
    const float inv = 1.0f / (float)TT;
    g_feat4[(size_t)plane * HW4 + p4] = make_float4(
        (a0.x + a1.x + a2.x + a3.x) * inv,
        (a0.y + a1.y + a2.y + a3.y) * inv,
        (a0.z + a1.z + a2.z + a3.z) * inv,
        (a0.w + a1.w + a2.w + a3.w) * inv);
}

// ============================================================
// Kernel 2: ROI pooling, separable weights, branch-free inner loop.
// Lane layout adapts to rect width (8/16/32 lanes along x). Per lane:
// wxv = WX[xx] hoisted (0 outside support), inner row: w = WY[yy]*wxv,
// then CPW unconditional FMAs (feat reads past rect hit zeros/pad).
// ============================================================
template <int XL>   // lanes along x (8, 16 or 32)
__device__ __forceinline__ void roi_accum(
    const float* __restrict__ fp0, const float* wy_s, const float wxv,
    const int4 rc, const int lane, const int xx, float* a) {
    const int yo = lane / XL;                 // 0..(32/XL-1)
    #pragma unroll 2
    for (int yy = rc.z + yo; yy <= rc.w; yy += 32 / XL) {
        const int p = yy * WW + xx;
        const float w = wy_s[yy] * wxv;
        #pragma unroll
        for (int k = 0; k < CPW; ++k)
            a[k] += w * fp0[k * HW + p];
    }
}

__global__ void __launch_bounds__(256) roi_kernel() {
    __shared__ float wx_s[WW], wy_s[HH];
    const int roi = blockIdx.x;
    const int cg  = blockIdx.y;            // 0..5
    const int tid = threadIdx.x, warp = tid >> 5, lane = tid & 31;

    const int4 rc = g_rect[roi];
    float* __restrict__ rmean = (float*)g_rmean4;
    if (rc.x > rc.y) {                     // empty roi (uniform branch)
        if (tid < CPB) rmean[roi * CC + cg * CPB + tid] = 0.f;
        return;
    }

    if (tid < WW) wx_s[tid] = g_wx[roi][tid];
    if (tid < HH) wy_s[tid] = g_wy[roi][tid];
    __syncthreads();

    const int b = g_broi[roi];
    const int c0 = cg * CPB + warp * CPW;
    const float* __restrict__ fp0 =
        (const float*)g_feat4 + (size_t)(b * CC + c0) * HW;

    float a[CPW];
    #pragma unroll
    for (int k = 0; k < CPW; ++k) a[k] = 0.f;

    const int wspan = rc.y - rc.x + 1;     // uniform across block
    if (wspan <= 8) {
        const int xx = rc.x + (lane & 7);
        const float wxv = (xx < WW) ? wx_s[xx] : 0.f;   // 0 outside support
        roi_accum<8>(fp0, wy_s, wxv, rc, lane, xx, a);
    } else if (wspan <= 16) {
        const int xx = rc.x + (lane & 15);
        const float wxv = (xx < WW) ? wx_s[xx] : 0.f;
        roi_accum<16>(fp0, wy_s, wxv, rc, lane, xx, a);
    } else {
        const int xx = rc.x + lane;
        const float wxv = (xx < WW) ? wx_s[xx] : 0.f;
        roi_accum<32>(fp0, wy_s, wxv, rc, lane, xx, a);
    }

    #pragma unroll
    for (int k = 0; k < CPW; ++k) {
        #pragma unroll
        for (int o = 16; o; o >>= 1) a[k] += __shfl_xor_sync(0xffffffffu, a[k], o);
    }
    if (lane == 0) {
        float* __restrict__ dst = rmean + roi * CC + c0;
        #pragma unroll
        for (int k = 0; k < CPW; ++k) dst[k] = a[k];
    }
}

// ============================================================
// Kernel 3: layer-1 GEMV partials with packed f32x2 math (FFMA2).
// 1024 blocks (64 quads x 16 jg), 8 neurons/block, 4 ROIs each.
// ============================================================
__global__ void __launch_bounds__(256) mlp_kernel(
    const float* __restrict__ w1, const float* __restrict__ b1) {
    __shared__ ulonglong2 r4[4 * CC4];
    __shared__ float part[8][4];
    const int tid = threadIdx.x, warp = tid >> 5, lane = tid & 31;
    const int roi0 = blockIdx.x * 4;
    const int jg = blockIdx.y;

    const ulonglong2* __restrict__ src = (const ulonglong2*)g_rmean4;
    for (int i = tid; i < 4 * CC4; i += 256)
        r4[i] = src[roi0 * CC4 + i];
    __syncthreads();

    const int j = jg * 8 + warp;
    const ulonglong2* __restrict__ wr = (const ulonglong2*)(w1 + j * CC);

    ull a0 = 0ull, a1 = 0ull, a2 = 0ull, a3 = 0ull;   // packed (+0,+0)
    for (int k = lane; k < CC4; k += 32) {
        const ulonglong2 w = wr[k];
        const ulonglong2 v0 = r4[k];
        const ulonglong2 v1 = r4[CC4 + k];
        const ulonglong2 v2 = r4[2 * CC4 + k];
        const ulonglong2 v3 = r4[3 * CC4 + k];
        a0 = ffma2(w.x, v0.x, a0); a0 = ffma2(w.y, v0.y, a0);
        a1 = ffma2(w.x, v1.x, a1); a1 = ffma2(w.y, v1.y, a1);
        a2 = ffma2(w.x, v2.x, a2); a2 = ffma2(w.y, v2.y, a2);
        a3 = ffma2(w.x, v3.x, a3); a3 = ffma2(w.y, v3.y, a3);
    }
    float s0 = hsum2(a0), s1 = hsum2(a1), s2 = hsum2(a2), s3 = hsum2(a3);
    #pragma unroll
    for (int o = 16; o; o >>= 1) {
        s0 += __shfl_xor_sync(0xffffffffu, s0, o);
        s1 += __shfl_xor_sync(0xffffffffu, s1, o);
        s2 += __shfl_xor_sync(0xffffffffu, s2, o);
        s3 += __shfl_xor_sync(0xffffffffu, s3, o);
    }
    if (lane == 0) {
        float bj = b1[j], vj = g_v[j];
        part[warp][0] = vj * fmaxf(s0 + bj, 0.f);
        part[warp][1] = vj * fmaxf(s1 + bj, 0.f);
        part[warp][2] = vj * fmaxf(s2 + bj, 0.f);
        part[warp][3] = vj * fmaxf(s3 + bj, 0.f);
    }
    __syncthreads();
    if (tid < 4) {
        float s = 0.f;
        #pragma unroll
        for (int w = 0; w < 8; ++w) s += part[w][tid];
        g_part[(roi0 + tid) * NJG + jg] = s;
    }
}

// ============================================================
// Kernel 4: finalize. out[roi] = c0 + sum_jg part[roi][jg].
// ============================================================
__global__ void fin_kernel(float* __restrict__ out) {
    int roi = threadIdx.x;
    float s = g_c0;
    #pragma unroll
    for (int jg = 0; jg < NJG; ++jg) s += g_part[roi * NJG + jg];
    out[roi] = s;
}

// ============================================================
// launch
// ============================================================
extern "C" void kernel_launch(void* const* d_in, const int* in_sizes, int n_in,
                              void* d_out, int out_size) {
    const float* x    = (const float*)d_in[0];
    const float* bbox = (const float*)d_in[1];
    const float* w1   = (const float*)d_in[2];
    const float* b1   = (const float*)d_in[3];
    const float* w2   = (const float*)d_in[4];
    const float* b2   = (const float*)d_in[5];
    const float* w3   = (const float*)d_in[6];
    const float* b3   = (const float*)d_in[7];
    float* out = (float*)d_out;

    wp_kernel<<<273, 256>>>(bbox, w2, b2, w3, b3);
    mean_kernel<<<MEAN_BLOCKS, 256>>>(x);
    roi_kernel<<<dim3(RR, CC / CPB), 256>>>();
    mlp_kernel<<<dim3(RR / 4, NJG), 256>>>(w1, b1);
    fin_kernel<<<1, RR>>>(out);
}

// round 17
// speedup vs baseline: 1.0906x; 1.0262x over previous
#include <cuda_runtime.h>
#include <cuda_bf16.h>

#define BB 16
#define CC 528
#define CC4 132         // CC/4
#define TT 32
#define HH 28
#define WW 28
#define HW 784          // 28*28
#define HW4 196         // HW/4 (7 float4 groups per row)
#define RR 256
#define MAX_ITEMS (BB*CC*HW4)   // 1,655,808
#define MEAN_BLOCKS ((MAX_ITEMS + 255) / 256)  // 6468
#define CPW 11          // channels per warp-chunk (16 warps * 33 = 528; 33 = 3*11)

typedef unsigned long long ull;

// packed f32x2 fma: d = a*b + c on both halves (FFMA2 — PTX-only pattern)
__device__ __forceinline__ ull ffma2(ull a, ull b, ull c) {
    ull d;
    asm("fma.rn.f32x2 %0, %1, %2, %3;" : "=l"(d) : "l"(a), "l"(b), "l"(c));
    return d;
}
__device__ __forceinline__ float hsum2(ull a) {
    return __uint_as_float((unsigned)a) + __uint_as_float((unsigned)(a >> 32));
}

// ---- device scratch (no allocations allowed) ----
__device__ float  g_wx[RR][WW];       // separable ROI weights: wmap = WY ⊗ WX
__device__ float  g_wy[RR][HH];       // (zero outside support)
__device__ int4   g_rect[RR];         // padded rect: xmin,xmax,ymin,ymax (inclusive); xmin>xmax => empty
__device__ int    g_broi[RR];         // batch index per roi
__device__ float  g_v[128];           // folded w3 @ w2  (layers 2+3 are linear)
__device__ float  g_c0;               // folded bias
__device__ int    g_load[BB][HW4];    // per-batch compacted float4-group indices
__device__ int    g_nload[BB];        // count per batch
__device__ float4 g_feat4[BB * CC * HW4 + 16];  // temporal-mean features (26.5 MB, L2-resident)
                                                // +16 pad: branch-free pool loads may overrun the last
                                                // plane; pad is zero and weighted by wxv=0.
                                                // uncovered entries stay 0 (zero-initialized, never written)

// ============================================================
// Kernel 0 (fully fused prep), 273 blocks:
//   blocks 0..255  : per-ROI separable weights WX[28], WY[28]
//   blocks 256..271: per-batch cover: analytic rects + union mask + load list
//   block  272     : fold v = w3@w2, c0 = w3@b2 + b3
// ============================================================
__global__ void wp_kernel(const float* __restrict__ bbox,
                          const float* __restrict__ w2,
                          const float* __restrict__ b2,
                          const float* __restrict__ w3,
                          const float* __restrict__ b3) {
    const int tid = threadIdx.x;
    const int blk = blockIdx.x;

    if (blk == 272) {                        // fold layers 2+3
        int j = tid;
        if (j < 128) {
            float acc = 0.f;
            #pragma unroll
            for (int i = 0; i < 32; ++i) acc += w3[i] * w2[i * 128 + j];
            g_v[j] = acc;
            if (j == 0) {
                float c = b3[0];
                #pragma unroll
                for (int i = 0; i < 32; ++i) c += w3[i] * b2[i];
                g_c0 = c;
            }
        }
        return;
    }

    if (blk >= 256) {                        // ---- cover for batch b ----
        const int b = blk - 256;
        __shared__ unsigned char mask[HW4];
        __shared__ int4 srect[RR];           // unpadded rects of this batch's rois
        __shared__ int scnt;

        for (int i = tid; i < HW4; i += 256) mask[i] = 0;
        if (tid == 0) scnt = 0;
        __syncthreads();

        // one thread per roi: analytic rect (separable x/y bounds)
        {
            const float* bb = bbox + tid * 5;
            const int rb = (int)bb[0];
            if (rb == b) {
                const float x1 = bb[1] * 0.0625f - 0.5f;
                const float y1 = bb[2] * 0.0625f - 0.5f;
                const float x2 = bb[3] * 0.0625f - 0.5f;
                const float y2 = bb[4] * 0.0625f - 0.5f;
                const float bw = (x2 - x1) * 0.125f;
                const float bh = (y2 - y1) * 0.125f;
                int xmin = 1000, xmax = -1, ymin = 1000, ymax = -1;
                #pragma unroll
                for (int i = 0; i < 16; ++i) {
                    const float o = (float)i * 0.5f + 0.25f;
                    const float sx = x1 + o * bw;
                    if (sx > -1.0f && sx < (float)WW) {
                        float xc = fminf(fmaxf(sx, 0.f), (float)(WW - 1));
                        int x0 = (int)floorf(xc);
                        int x1i = min(x0 + 1, WW - 1);
                        xmin = min(xmin, x0); xmax = max(xmax, x1i);
                    }
                    const float sy = y1 + o * bh;
                    if (sy > -1.0f && sy < (float)HH) {
                        float yc = fminf(fmaxf(sy, 0.f), (float)(HH - 1));
                        int y0 = (int)floorf(yc);
                        int y1i = min(y0 + 1, HH - 1);
                        ymin = min(ymin, y0); ymax = max(ymax, y1i);
                    }
                }
                int4 rc_pad, rc_raw;
                if (xmax < 0 || ymax < 0) {
                    rc_pad = make_int4(1000, -1, 1000, -1);
                    rc_raw = rc_pad;
                } else {
                    rc_raw = make_int4(xmin, xmax, ymin, ymax);
                    rc_pad = make_int4(max(xmin - 1, 0), min(xmax + 1, WW - 1),
                                       max(ymin - 1, 0), min(ymax + 1, HH - 1));
                }
                g_rect[tid] = rc_pad;
                g_broi[tid] = rb;
                if (rc_raw.x <= rc_raw.y) {
                    int slot = atomicAdd(&scnt, 1);
                    srect[slot] = rc_raw;    // order irrelevant: mask union idempotent
                }
            }
        }
        __syncthreads();

        const int n = scnt;
        for (int r = 0; r < n; ++r) {
            const int4 rc = srect[r];
            const int g0 = rc.x >> 2, g1 = rc.y >> 2;
            const int cols = g1 - g0 + 1;
            const int tot = (rc.w - rc.z + 1) * cols;
            for (int i = tid; i < tot; i += 256) {
                int ry = i / cols, cx = i - ry * cols;
                mask[(rc.z + ry) * 7 + g0 + cx] = 1;
            }
        }
        __syncthreads();

        // warp-0 ballot compaction
        if (tid < 32) {
            const int lane = tid;
            int base = 0;
            #pragma unroll
            for (int ch = 0; ch < 7; ++ch) {
                const int i = ch * 32 + lane;
                const bool m = (i < HW4) && mask[i];
                const unsigned bal = __ballot_sync(0xffffffffu, m);
                if (m) g_load[b][base + __popc(bal & ((1u << lane) - 1))] = i;
                base += __popc(bal);
            }
            if (lane == 0) g_nload[b] = base;
        }
        return;
    }

    // ---- separable weights for roi = blk ----
    __shared__ float wx_s[WW], wy_s[HH];
    const int roi = blk;

    if (tid < WW) wx_s[tid] = 0.f;
    if (tid < HH) wy_s[tid] = 0.f;
    __syncthreads();

    const float* bb = bbox + roi * 5;
    const float x1 = bb[1] * 0.0625f - 0.5f;
    const float y1 = bb[2] * 0.0625f - 0.5f;
    const float x2 = bb[3] * 0.0625f - 0.5f;
    const float y2 = bb[4] * 0.0625f - 0.5f;
    const float bw = (x2 - x1) * 0.125f;   // /OUT(8)
    const float bh = (y2 - y1) * 0.125f;
    const float s = 1.0f / 16.0f;          // 1/256 split across the two factors

    if (tid < 16) {                        // x-samples
        const float sx = x1 + ((float)tid * 0.5f + 0.25f) * bw;
        if (sx > -1.0f && sx < (float)WW) {
            float xc = fminf(fmaxf(sx, 0.f), (float)(WW - 1));
            int x0 = (int)floorf(xc);
            int x1i = min(x0 + 1, WW - 1);
            float lx = xc - (float)x0;
            atomicAdd(&wx_s[x0],  (1.f - lx) * s);
            atomicAdd(&wx_s[x1i], lx * s);
        }
    } else if (tid < 32) {                 // y-samples
        const int i = tid - 16;
        const float sy = y1 + ((float)i * 0.5f + 0.25f) * bh;
        if (sy > -1.0f && sy < (float)HH) {
            float yc = fminf(fmaxf(sy, 0.f), (float)(HH - 1));
            int y0 = (int)floorf(yc);
            int y1i = min(y0 + 1, HH - 1);
            float ly = yc - (float)y0;
            atomicAdd(&wy_s[y0],  (1.f - ly) * s);
            atomicAdd(&wy_s[y1i], ly * s);
        }
    }
    __syncthreads();

    if (tid < WW) g_wx[roi][tid] = wx_s[tid];
    if (tid < HH) g_wy[roi][tid] = wy_s[tid];
}

// ============================================================
// Kernel 1 (HBM-bound, 81% DRAM — unchanged): temporal mean over
// covered groups, flat work list, 4 independent accumulator chains.
// ============================================================
__global__ void __launch_bounds__(256) mean_kernel(const float* __restrict__ x) {
    __shared__ int soff[BB + 1];
    __shared__ int sn4[BB];
    if (threadIdx.x == 0) {
        int acc = 0;
        #pragma unroll
        for (int b = 0; b < BB; ++b) {
            soff[b] = acc;
            int n = g_nload[b];
            sn4[b] = n;
            acc += n * CC;
        }
        soff[BB] = acc;
    }
    __syncthreads();

    const int item = blockIdx.x * 256 + threadIdx.x;
    if (item >= soff[BB]) return;

    int b = 0;
    while (item >= soff[b + 1]) ++b;
    const int rel = item - soff[b];
    const int n4 = sn4[b];
    const int c = rel / n4;
    const int j = rel - c * n4;
    const int p4 = g_load[b][j];
    const int plane = b * CC + c;

    const float4* __restrict__ xp =
        (const float4*)x + (size_t)plane * (TT * HW4) + p4;

    float4 a0 = make_float4(0.f, 0.f, 0.f, 0.f);
    float4 a1 = a0, a2 = a0, a3 = a0;
    #pragma unroll
    for (int t = 0; t < 8; ++t) {
        float4 v0 = __ldcs(xp + (t)      * HW4);
        float4 v1 = __ldcs(xp + (t + 8)  * HW4);
        float4 v2 = __ldcs(xp + (t + 16) * HW4);
        float4 v3 = __ldcs(xp + (t + 24) * HW4);
        a0.x += v0.x; a0.y += v0.y; a0.z += v0.z; a0.w += v0.w;
        a1.x += v1.x; a1.y += v1.y; a1.z += v1.z; a1.w += v1.w;
        a2.x += v2.x; a2.y += v2.y; a2.z += v2.z; a2.w += v2.w;
        a3.x += v3.x; a3.y += v3.y; a3.z += v3.z; a3.w += v3.w;
    }
    const float inv = 1.0f / (float)TT;
    g_feat4[(size_t)plane * HW4 + p4] = make_float4(
        (a0.x + a1.x + a2.x + a3.x) * inv,
        (a0.y + a1.y + a2.y + a3.y) * inv,
        (a0.z + a1.z + a2.z + a3.z) * inv,
        (a0.w + a1.w + a2.w + a3.w) * inv);
}

// ============================================================
// Kernel 2 (fused ROI pool + MLP + output): one block per ROI, 512 thr.
// Phase 1: 16 warps x 33 channels (3 chunks of 11-channel ILP), separable
//          branch-free inner loop -> r[528] in smem (no global round-trip).
// Phase 2: each warp dots 8 neurons (FFMA2, 8 accumulators share each v
//          load), folds relu*v; warp 0 reduces 16 partials -> out[roi].
// Fixed-order reductions => deterministic. All branches around barriers
// are block-uniform (rc identical for all threads of the block).
// ============================================================
template <int XL>   // lanes along x (8, 16 or 32)
__device__ __forceinline__ void roi_accum(
    const float* __restrict__ fp0, const float* wy_s, const float wxv,
    const int4 rc, const int lane, const int xx, float* a) {
    const int yo = lane / XL;                 // 0..(32/XL-1)
    #pragma unroll 2
    for (int yy = rc.z + yo; yy <= rc.w; yy += 32 / XL) {
        const int p = yy * WW + xx;
        const float w = wy_s[yy] * wxv;
        #pragma unroll
        for (int k = 0; k < CPW; ++k)
            a[k] += w * fp0[k * HW + p];
    }
}

__global__ void __launch_bounds__(512) roimlp_kernel(
    const float* __restrict__ w1, const float* __restrict__ b1,
    float* __restrict__ out) {
    __shared__ float wx_s[WW], wy_s[HH];
    __shared__ __align__(16) float r[CC];
    __shared__ float part[16];
    const int roi = blockIdx.x;
    const int tid = threadIdx.x, warp = tid >> 5, lane = tid & 31;

    const int4 rc = g_rect[roi];
    const bool empty = (rc.x > rc.y);        // block-uniform

    if (empty) {
        for (int i = tid; i < CC; i += 512) r[i] = 0.f;
    } else {
        if (tid < WW) wx_s[tid] = g_wx[roi][tid];
        if (tid < HH) wy_s[tid] = g_wy[roi][tid];
        __syncthreads();

        const int b = g_broi[roi];
        const int wspan = rc.y - rc.x + 1;   // uniform across block

        #pragma unroll
        for (int chunk = 0; chunk < 3; ++chunk) {
            const int c0 = warp * 33 + chunk * CPW;
            const float* __restrict__ fp0 =
                (const float*)g_feat4 + (size_t)(b * CC + c0) * HW;

            float a[CPW];
            #pragma unroll
            for (int k = 0; k < CPW; ++k) a[k] = 0.f;

            if (wspan <= 8) {
                const int xx = rc.x + (lane & 7);
                const float wxv = (xx < WW) ? wx_s[xx] : 0.f;
                roi_accum<8>(fp0, wy_s, wxv, rc, lane, xx, a);
            } else if (wspan <= 16) {
                const int xx = rc.x + (lane & 15);
                const float wxv = (xx < WW) ? wx_s[xx] : 0.f;
                roi_accum<16>(fp0, wy_s, wxv, rc, lane, xx, a);
            } else {
                const int xx = rc.x + lane;
                const float wxv = (xx < WW) ? wx_s[xx] : 0.f;
                roi_accum<32>(fp0, wy_s, wxv, rc, lane, xx, a);
            }

            #pragma unroll
            for (int k = 0; k < CPW; ++k) {
                #pragma unroll
                for (int o = 16; o; o >>= 1)
                    a[k] += __shfl_xor_sync(0xffffffffu, a[k], o);
            }
            if (lane == 0) {
                #pragma unroll
                for (int k = 0; k < CPW; ++k) r[c0 + k] = a[k];
            }
        }
    }
    __syncthreads();

    // ---- phase 2: MLP over smem r ----
    const ulonglong2* __restrict__ rsh = (const ulonglong2*)r;
    const int j0 = warp * 8;

    ull acc[8];
    #pragma unroll
    for (int i = 0; i < 8; ++i) acc[i] = 0ull;

    for (int k = lane; k < CC4; k += 32) {
        const ulonglong2 v = rsh[k];
        #pragma unroll
        for (int i = 0; i < 8; ++i) {
            const ulonglong2 w =
                ((const ulonglong2*)(w1 + (j0 + i) * CC))[k];
            acc[i] = ffma2(w.x, v.x, acc[i]);
            acc[i] = ffma2(w.y, v.y, acc[i]);
        }
    }
    float o = 0.f;
    #pragma unroll
    for (int i = 0; i < 8; ++i) {
        float s = hsum2(acc[i]);
        #pragma unroll
        for (int sh = 16; sh; sh >>= 1) s += __shfl_xor_sync(0xffffffffu, s, sh);
        if (lane == 0) o += g_v[j0 + i] * fmaxf(s + b1[j0 + i], 0.f);
    }
    if (lane == 0) part[warp] = o;
    __syncthreads();

    if (tid < 32) {
        float s = (tid < 16) ? part[tid] : 0.f;
        #pragma unroll
        for (int sh = 8; sh; sh >>= 1) s += __shfl_xor_sync(0xffffffffu, s, sh);
        if (tid == 0) out[roi] = s + g_c0;
    }
}

// ============================================================
// launch
// ============================================================
extern "C" void kernel_launch(void* const* d_in, const int* in_sizes, int n_in,
                              void* d_out, int out_size) {
    const float* x    = (const float*)d_in[0];
    const float* bbox = (const float*)d_in[1];
    const float* w1   = (const float*)d_in[2];
    const float* b1   = (const float*)d_in[3];
    const float* w2   = (const float*)d_in[4];
    const float* b2   = (const float*)d_in[5];
    const float* w3   = (const float*)d_in[6];
    const float* b3   = (const float*)d_in[7];
    float* out = (float*)d_out;

    wp_kernel<<<273, 256>>>(bbox, w2, b2, w3, b3);
    mean_kernel<<<MEAN_BLOCKS, 256>>>(x);
    roimlp_kernel<<<RR, 512>>>(w1, b1, out);
}